// round 7
// baseline (speedup 1.0000x reference)
#include <cuda_runtime.h>
#include <cuda_fp16.h>
#include <math.h>
#include <stdint.h>

#define NF 65536
#define NB 8
#define JQ 64
#define NSEC 224
#define NCHAN 289
#define LG 768
#define GTAPS 1537
#define KPHI 1024
#define INV_N (1.0f/65536.0f)
#define FO_CHUNK 64
#define SO_CHUNK 256

// ---------------- static device storage ----------------
static __device__ float2  TW[NF];
static __device__ float   GF[GTAPS];
static __device__ float2  d_xtmp[  8u*65536u];       // x fwd intermediate (fp32)
static __device__ float2  d_xf  [  8u*65536u];       // spectra of x (fp32)
static __device__ float2  d_pA  [ (size_t)FO_CHUNK*65536u];  // FO passA->passB (fp32, L2)
static __device__ float2  d_pB  [ (size_t)FO_CHUNK*65536u];  // FO passB->rowfft (fp32, L2)
static __device__ __half2 d_pS  [ (size_t)SO_CHUNK*65536u];  // SO passA->passB (fp16, L2), 4x true
static __device__ __half2 d_u1f [ 512u*65536u];      // FFT(|U1|) fp16, scaled 1/4
static __device__ float   d_sp1 [  512u*4096u];
static __device__ float   d_sp2 [ 1792u*4096u];

static __device__ const float2 W16T[16] = {
  { 1.0f, 0.0f},
  { 0.9238795325112867f, 0.3826834323650898f},
  { 0.7071067811865476f, 0.7071067811865476f},
  { 0.3826834323650898f, 0.9238795325112867f},
  { 0.0f, 1.0f},
  {-0.3826834323650898f, 0.9238795325112867f},
  {-0.7071067811865476f, 0.7071067811865476f},
  {-0.9238795325112867f, 0.3826834323650898f},
  {-1.0f, 0.0f},
  {-0.9238795325112867f,-0.3826834323650898f},
  {-0.7071067811865476f,-0.7071067811865476f},
  {-0.3826834323650898f,-0.9238795325112867f},
  { 0.0f,-1.0f},
  { 0.3826834323650898f,-0.9238795325112867f},
  { 0.7071067811865476f,-0.7071067811865476f},
  { 0.9238795325112867f,-0.3826834323650898f}
};

// ---------------- complex helpers ----------------
__device__ __forceinline__ float2 cadd(float2 a, float2 b){ return make_float2(a.x+b.x, a.y+b.y); }
__device__ __forceinline__ float2 csub(float2 a, float2 b){ return make_float2(a.x-b.x, a.y-b.y); }
__device__ __forceinline__ float2 cmul(float2 a, float2 b){ return make_float2(a.x*b.x-a.y*b.y, a.x*b.y+a.y*b.x); }
__device__ __forceinline__ float2 h2f(__half2 h){ return __half22float2(h); }
__device__ __forceinline__ __half2 f2h(float2 v){ return __float22half2_rn(v); }
template<int S> __device__ __forceinline__ float2 mul_i(float2 a){
  return (S>0) ? make_float2(-a.y, a.x) : make_float2(a.y, -a.x);
}
template<int S> __device__ __forceinline__ void dft4(float2&a, float2&b, float2&c, float2&d){
  float2 t0=cadd(a,c), t1=csub(a,c), t2=cadd(b,d), t3=mul_i<S>(csub(b,d));
  a=cadd(t0,t2); c=csub(t0,t2); b=cadd(t1,t3); d=csub(t1,t3);
}
template<int S> __device__ __forceinline__ float2 w16(int m){
  float2 w = W16T[m];
  if (S < 0) w.y = -w.y;
  return w;
}
template<int S> __device__ __forceinline__ void fft16(float2 v[16]){
  #pragma unroll
  for (int n0=0; n0<4; n0++) dft4<S>(v[n0], v[n0+4], v[n0+8], v[n0+12]);
  #pragma unroll
  for (int n0=1; n0<4; n0++)
    #pragma unroll
    for (int k1=1; k1<4; k1++)
      v[n0+4*k1] = cmul(v[n0+4*k1], w16<S>(n0*k1));
  float2 o[16];
  #pragma unroll
  for (int k1=0; k1<4; k1++){
    float2 a=v[4*k1+0], b=v[4*k1+1], c=v[4*k1+2], d=v[4*k1+3];
    dft4<S>(a,b,c,d);
    o[k1]=a; o[k1+4]=b; o[k1+8]=c; o[k1+12]=d;
  }
  #pragma unroll
  for (int i=0;i<16;i++) v[i]=o[i];
}

// padded-row transpose (conflict-free with FFT-slot f in LOW 4 bits of tid)
template<int S> __device__ __forceinline__ void fft256_pad(float2 v[16], int i, float2* sm){
  fft16<S>(v);
  #pragma unroll
  for (int k1=1;k1<16;k1++){
    float2 w = TW[(i*k1*256)&65535];
    if (S<0) w.y = -w.y;
    v[k1] = cmul(v[k1], w);
  }
  #pragma unroll
  for (int k1=0;k1<16;k1++) sm[k1*16+i] = v[k1];
  __syncthreads();
  #pragma unroll
  for (int n0=0;n0<16;n0++) v[n0] = sm[i*16+n0];
  fft16<S>(v);
}

// swizzled transpose (conflict-free with lane i in LOW 4 bits of tid)
template<int S> __device__ __forceinline__ void fft256_swz(float2 v[16], int i, float2* sm){
  fft16<S>(v);
  #pragma unroll
  for (int k1=1;k1<16;k1++){
    float2 w = TW[(i*k1*256)&65535];
    if (S<0) w.y = -w.y;
    v[k1] = cmul(v[k1], w);
  }
  #pragma unroll
  for (int k1=0;k1<16;k1++) sm[k1*16 + ((i+k1)&15)] = v[k1];
  __syncthreads();
  #pragma unroll
  for (int n0=0;n0<16;n0++) v[n0] = sm[i*16 + ((n0+i)&15)];
  fft16<S>(v);
}

// partial lowpass over this block's 16 stride-256 combs
__device__ __forceinline__ void conv_partial(const float* u_s, const float* gf_s,
                                             int bx, int m, float* sp)
{
  float acc = 0.0f;
  #pragma unroll
  for (int f2=0; f2<16; f2++){
    const int q = bx*16 + f2 + 768;
    #pragma unroll
    for (int d=-3; d<=3; d++){
      int tap = d*256 + q;
      if (tap >= 0 && tap <= 1536)
        acc += gf_s[tap] * u_s[f2*257 + ((m + d) & 255)];
    }
  }
  sp[bx*256 + m] = acc;
}

// ---------------- setup kernels ----------------
__global__ void k_tw(){
  int k = blockIdx.x*blockDim.x + threadIdx.x;
  double a = 6.283185307179586476925286766559 * (double)k / 65536.0;
  TW[k] = make_float2((float)cos(a), (float)sin(a));
}
__global__ void k_g(){
  int i = blockIdx.x*blockDim.x + threadIdx.x;
  if (i >= GTAPS) return;
  int tt = i - LG; if (tt < 0) tt = -tt;
  const float invden = 1.0f/(65536.0f*(0.35f/256.0f));
  float acc = 1.0f;
  for (int k=1; k<=KPHI; k++){
    float z = (float)k * invden;
    float p = expf(-0.5f*z*z);
    int m = (k*tt) & 65535;
    acc += 2.0f * p * TW[m].x;
  }
  GF[i] = acc * INV_N;
}

// ---------------- FFT pass kernels ----------------
__global__ void __launch_bounds__(256) k_fwd_col_x(const float* __restrict__ x,
                                                   float2* __restrict__ out)
{
  __shared__ float2 sm[16*257];
  const int f = threadIdx.x & 15, i = threadIdx.x >> 4;
  const int col = blockIdx.x*16 + f;
  const size_t base = (size_t)blockIdx.y * NF;
  float2 v[16];
  #pragma unroll
  for (int r=0;r<16;r++) v[r] = make_float2(x[base + (r*16+i)*256 + col], 0.0f);
  fft256_pad<-1>(v, i, sm + f*257);
  #pragma unroll
  for (int k2=0;k2<16;k2++){
    int K1 = k2*16 + i;
    float2 w = TW[(col*K1)&65535]; w.y = -w.y;
    out[base + K1*256 + col] = cmul(v[k2], w);
  }
}

// fp32 row pass (x path)
__global__ void __launch_bounds__(256) k_fwd_row(const float2* __restrict__ in,
                                                 float2* __restrict__ out)
{
  __shared__ float2 sm[16*256];
  const int i = threadIdx.x & 15, f = threadIdx.x >> 4;
  const int row = blockIdx.x*16 + f;
  const size_t base = (size_t)blockIdx.y * NF;
  float2 v[16];
  #pragma unroll
  for (int r=0;r<16;r++) v[r] = in[base + row*256 + r*16 + i];
  fft256_swz<-1>(v, i, sm + f*256);
  #pragma unroll
  for (int k2=0;k2<16;k2++) out[base + row*256 + k2*16 + i] = v[k2];
}

// row pass: fp32 local pong -> fp16 global u1f (x 0.25)
__global__ void __launch_bounds__(256) k_fwd_row_u1(const float2* __restrict__ in,
                                                    __half2* __restrict__ out, int tbase)
{
  __shared__ float2 sm[16*256];
  const int i = threadIdx.x & 15, f = threadIdx.x >> 4;
  const int row = blockIdx.x*16 + f;
  float2 v[16];
  #pragma unroll
  for (int r=0;r<16;r++) v[r] = in[(size_t)blockIdx.y*NF + row*256 + r*16 + i];
  fft256_swz<-1>(v, i, sm + f*256);
  #pragma unroll
  for (int k2=0;k2<16;k2++){
    float2 o = v[k2];
    out[(size_t)(tbase+blockIdx.y)*NF + row*256 + k2*16 + i] =
      f2h(make_float2(o.x*0.25f, o.y*0.25f));
  }
}

// FO inverse pass A (fp32 xf -> fp32 local ping), fused pruned psi1*1/N
__global__ void __launch_bounds__(256) k_invA1(const float2* __restrict__ in,
                                               float2* __restrict__ out, int tbase)
{
  __shared__ float2 sm[16*256];
  const int i = threadIdx.x & 15, f = threadIdx.x >> 4;
  const int K1 = blockIdx.x*16 + f;
  const int ti = tbase + blockIdx.y;
  const int b = ti >> 6, ch = ti & 63;
  const float xi   = 0.35f * exp2f(-(float)ch * 0.125f);
  const float invs = 8.0f / xi;
  const float2* src = in + (size_t)b*NF;

  float2 v[16];
  #pragma unroll
  for (int r=0;r<16;r++){
    int k2c = r*16 + i;
    int k = k2c*256 + K1;
    float fn = (k < 32768) ? (float)k * INV_N : ((float)k - 65536.0f) * INV_N;
    float z = (fn - xi) * invs;
    float g = expf(-0.5f*z*z);
    if (g > 1e-12f){
      float2 X = src[K1*256 + k2c];
      float s = g * INV_N;
      v[r] = make_float2(X.x*s, X.y*s);
    } else v[r] = make_float2(0.0f, 0.0f);
  }
  fft256_swz<1>(v, i, sm + f*256);
  #pragma unroll
  for (int k2=0;k2<16;k2++){
    int n2 = k2*16 + i;
    out[(size_t)blockIdx.y*NF + K1*256 + n2] = cmul(v[k2], TW[(n2*K1)&65535]);
  }
}

// SO inverse pass A (fp16 u1f(scale 1/4) -> fp16 local ping, 4x true).
// s = g * 16/N: x4 undoes u1f's 1/4, another x4 keeps pS large for fp16.
__global__ void __launch_bounds__(256) k_invA2(const __half2* __restrict__ in,
                                               __half2* __restrict__ out, int tbase)
{
  __shared__ float2 sm[16*256];
  const int i = threadIdx.x & 15, f = threadIdx.x >> 4;
  const int K1 = blockIdx.x*16 + f;
  const int ti = tbase + blockIdx.y;
  const int b = ti / NSEC;
  const int s0 = ti - b*NSEC;
  int j2 = 1;
  #pragma unroll
  for (int q=1; q<7; q++) if (s0 >= 4*q*(q+1)) j2 = q+1;
  const int ch = s0 - 4*j2*(j2-1);
  const float xi   = 0.35f * exp2f(-(float)j2);
  const float invs = 1.0f / (0.6f * xi);
  const __half2* src = in + ((size_t)b*JQ + ch)*NF;

  float2 v[16];
  #pragma unroll
  for (int r=0;r<16;r++){
    int k2c = r*16 + i;
    int k = k2c*256 + K1;
    float fn = (k < 32768) ? (float)k * INV_N : ((float)k - 65536.0f) * INV_N;
    float z = (fn - xi) * invs;
    float g = expf(-0.5f*z*z);
    if (g > 1e-12f){
      float2 X = h2f(src[K1*256 + k2c]);
      float s = g * (16.0f*INV_N);
      v[r] = make_float2(X.x*s, X.y*s);
    } else v[r] = make_float2(0.0f, 0.0f);
  }
  fft256_swz<1>(v, i, sm + f*256);
  #pragma unroll
  for (int k2=0;k2<16;k2++){
    int n2 = k2*16 + i;
    out[(size_t)blockIdx.y*NF + K1*256 + n2] = f2h(cmul(v[k2], TW[(n2*K1)&65535]));
  }
}

// FO pass B: col IFFT -> |.| -> lowpass partial -> col FFT -> twiddle (fp32 local)
__global__ void __launch_bounds__(256) k_fo_b(const float2* __restrict__ T,
                                              float2* __restrict__ out,
                                              float* __restrict__ sp1, int tbase)
{
  __shared__ __align__(16) char smraw[16*257*sizeof(float2)];
  float2* sm   = (float2*)smraw;
  float*  u_s  = (float*)smraw;
  float*  gf_s = (float*)smraw + 16*257;

  const int f = threadIdx.x & 15, i = threadIdx.x >> 4;
  const int tid = threadIdx.x;
  const int n2 = blockIdx.x*16 + f;
  const size_t base = (size_t)blockIdx.y * NF;
  float2 v[16];
  #pragma unroll
  for (int r=0;r<16;r++) v[r] = T[base + (r*16+i)*256 + n2];
  fft256_pad<1>(v, i, sm + f*257);
  __syncthreads();
  #pragma unroll
  for (int k2=0;k2<16;k2++)
    u_s[f*257 + k2*16 + i] = sqrtf(v[k2].x*v[k2].x + v[k2].y*v[k2].y);
  for (int t=tid; t<GTAPS; t+=256) gf_s[t] = GF[t];
  __syncthreads();
  conv_partial(u_s, gf_s, blockIdx.x, tid, sp1 + (size_t)(tbase+blockIdx.y)*4096);
  __syncthreads();
  #pragma unroll
  for (int r=0;r<16;r++) v[r] = make_float2(u_s[f*257 + r*16 + i], 0.0f);
  __syncthreads();
  fft256_pad<-1>(v, i, sm + f*257);
  #pragma unroll
  for (int k2=0;k2<16;k2++){
    int K1 = k2*16 + i;
    float2 w = TW[(n2*K1)&65535]; w.y = -w.y;
    out[base + K1*256 + n2] = cmul(v[k2], w);
  }
}

// SO pass B: col IFFT -> 0.25*|.| (undo pS 4x) -> lowpass partial
__global__ void __launch_bounds__(256) k_invB_abs(const __half2* __restrict__ T,
                                                  float* __restrict__ sp2, int tbase)
{
  __shared__ __align__(16) char smraw[16*257*sizeof(float2)];
  float2* sm   = (float2*)smraw;
  float*  u_s  = (float*)smraw;
  float*  gf_s = (float*)smraw + 16*257;

  const int f = threadIdx.x & 15, i = threadIdx.x >> 4;
  const int tid = threadIdx.x;
  const int n2 = blockIdx.x*16 + f;
  const size_t base = (size_t)blockIdx.y * NF;
  float2 v[16];
  #pragma unroll
  for (int r=0;r<16;r++) v[r] = h2f(T[base + (r*16+i)*256 + n2]);
  fft256_pad<1>(v, i, sm + f*257);
  __syncthreads();
  #pragma unroll
  for (int k2=0;k2<16;k2++)
    u_s[f*257 + k2*16 + i] = 0.25f*sqrtf(v[k2].x*v[k2].x + v[k2].y*v[k2].y);
  for (int t=tid; t<GTAPS; t+=256) gf_s[t] = GF[t];
  __syncthreads();
  conv_partial(u_s, gf_s, blockIdx.x, tid, sp2 + (size_t)(tbase+blockIdx.y)*4096);
}

// ---------------- S0 conv (x only) ----------------
#define CONV_OUT 32
#define CONV_WIN ((CONV_OUT-1)*256 + GTAPS)
__global__ void __launch_bounds__(256) k_conv_x(const float* __restrict__ x,
                                                float* __restrict__ out)
{
  const int grp = blockIdx.x, b = blockIdx.y;
  const float* src = x + (size_t)b*NF;
  __shared__ float win[CONV_WIN + 3];
  __shared__ float gs[GTAPS];
  const int tid = threadIdx.x;
  const int w0 = grp*(CONV_OUT*256) - LG;
  for (int i=tid; i<CONV_WIN; i+=256) win[i] = src[(w0 + i) & 65535];
  for (int i=tid; i<GTAPS; i+=256) gs[i] = GF[i];
  __syncthreads();
  const int warp = tid >> 5, lane = tid & 31;
  #pragma unroll
  for (int oo=0; oo<CONV_OUT/8; oo++){
    const int o = warp*(CONV_OUT/8) + oo;
    const int off = o * 256;
    float acc = 0.0f;
    for (int i=lane; i<GTAPS; i+=32) acc += gs[i] * win[off + i];
    #pragma unroll
    for (int d=16; d; d>>=1) acc += __shfl_down_sync(0xffffffffu, acc, d);
    if (lane == 0){
      int n = grp*CONV_OUT + o;
      float mag = sqrtf(acc*acc + 1e-8f);
      out[(size_t)b*NCHAN*256 + n] = logf(mag + 1e-8f);
    }
  }
}

// ---------------- epilogue: sum 16 partials, log ----------------
__global__ void __launch_bounds__(256) k_log(const float* __restrict__ sp1,
                                             const float* __restrict__ sp2,
                                             float* __restrict__ out)
{
  const int row = blockIdx.x;
  const int b = row / 288, cm1 = row - b*288;
  const int m = threadIdx.x;
  const float* base = (cm1 < 64)
    ? sp1 + (size_t)(b*JQ   + cm1     )*4096
    : sp2 + (size_t)(b*NSEC + cm1 - 64)*4096;
  float S = 0.0f;
  #pragma unroll
  for (int k=0;k<16;k++) S += base[k*256 + m];
  float mag = sqrtf(S*S + 1e-8f);
  out[((size_t)b*NCHAN + 1 + cm1)*256 + m] = logf(mag + 1e-8f);
}

__global__ void k_zero(float* p, int n){
  int i = blockIdx.x*blockDim.x + threadIdx.x;
  if (i < n) p[i] = 0.0f;
}

// ---------------- launch ----------------
extern "C" void kernel_launch(void* const* d_in, const int* in_sizes, int n_in,
                              void* d_out, int out_size)
{
  (void)in_sizes; (void)n_in;
  const float* x = (const float*)d_in[0];
  float* out = (float*)d_out;

  float2 *xtmp, *xf, *pA, *pB;
  __half2 *pS, *u1f;
  float *sp1, *sp2;
  cudaGetSymbolAddress((void**)&xtmp, d_xtmp);
  cudaGetSymbolAddress((void**)&xf,   d_xf);
  cudaGetSymbolAddress((void**)&pA,   d_pA);
  cudaGetSymbolAddress((void**)&pB,   d_pB);
  cudaGetSymbolAddress((void**)&pS,   d_pS);
  cudaGetSymbolAddress((void**)&u1f,  d_u1f);
  cudaGetSymbolAddress((void**)&sp1,  d_sp1);
  cudaGetSymbolAddress((void**)&sp2,  d_sp2);

  k_tw<<<256, 256>>>();
  k_g <<<7,   256>>>();

  // forward FFT of x (8 transforms, fp32)
  k_fwd_col_x<<<dim3(16,8), 256>>>(x, xtmp);
  k_fwd_row  <<<dim3(16,8), 256>>>(xtmp, xf);

  // first order: 8 chunks of 64 transforms, intermediates L2-resident fp32
  for (int c = 0; c < 512/FO_CHUNK; c++){
    int tb = c*FO_CHUNK;
    k_invA1     <<<dim3(16,FO_CHUNK), 256>>>(xf, pA, tb);
    k_fo_b      <<<dim3(16,FO_CHUNK), 256>>>(pA, pB, sp1, tb);
    k_fwd_row_u1<<<dim3(16,FO_CHUNK), 256>>>(pB, u1f, tb);
  }

  // second order: 7 chunks of 256 transforms, intermediate L2-resident fp16
  for (int c = 0; c < 1792/SO_CHUNK; c++){
    int tb = c*SO_CHUNK;
    k_invA2   <<<dim3(16,SO_CHUNK), 256>>>(u1f, pS, tb);
    k_invB_abs<<<dim3(16,SO_CHUNK), 256>>>(pS, sp2, tb);
  }

  // S0 + epilogue
  k_conv_x<<<dim3(8, NB), 256>>>(x, out);
  k_log   <<<2304, 256>>>(sp1, sp2, out);

  // imaginary half = zeros
  int half = out_size / 2;
  k_zero<<<(half + 255)/256, 256>>>(out + half, half);
}

// round 8
// speedup vs baseline: 1.0710x; 1.0710x over previous
#include <cuda_runtime.h>
#include <cuda_fp16.h>
#include <math.h>
#include <stdint.h>

#define NF 65536
#define NB 8
#define JQ 64
#define NSEC 224
#define NCHAN 289
#define LG 768
#define GTAPS 1537
#define KPHI 1024
#define INV_N (1.0f/65536.0f)
#define ZCUT 7.4395f   // e^{-0.5*7.4395^2} ~ 1e-12

// ---------------- static device storage ----------------
static __device__ float2  TW[NF];
static __device__ float   GF[GTAPS];
static __device__ float   PS1[(size_t)JQ*NF];        // psi1 tables
static __device__ float   PS2[(size_t)8*NF];         // psi2 tables
static __device__ float2  d_xtmp[  8u*65536u];
static __device__ float2  d_xf  [  8u*65536u];
static __device__ float2  d_p1a [ 512u*65536u];      // FO passA->passB (fp32)
static __device__ float2  d_p1b [ 512u*65536u];      // FO passB->rowfft (fp32)
static __device__ __half2 d_p2  [(size_t)1792u*65536u]; // SO passA->passB (fp16, 4x true)
static __device__ __half2 d_u1f [ 512u*65536u];      // FFT(|U1|) fp16, scaled 1/4
static __device__ float   d_sp1 [  512u*4096u];
static __device__ float   d_sp2 [ 1792u*4096u];

static __device__ const float2 W16T[16] = {
  { 1.0f, 0.0f},
  { 0.9238795325112867f, 0.3826834323650898f},
  { 0.7071067811865476f, 0.7071067811865476f},
  { 0.3826834323650898f, 0.9238795325112867f},
  { 0.0f, 1.0f},
  {-0.3826834323650898f, 0.9238795325112867f},
  {-0.7071067811865476f, 0.7071067811865476f},
  {-0.9238795325112867f, 0.3826834323650898f},
  {-1.0f, 0.0f},
  {-0.9238795325112867f,-0.3826834323650898f},
  {-0.7071067811865476f,-0.7071067811865476f},
  {-0.3826834323650898f,-0.9238795325112867f},
  { 0.0f,-1.0f},
  { 0.3826834323650898f,-0.9238795325112867f},
  { 0.7071067811865476f,-0.7071067811865476f},
  { 0.9238795325112867f,-0.3826834323650898f}
};

// ---------------- helpers ----------------
__device__ __forceinline__ float2 cadd(float2 a, float2 b){ return make_float2(a.x+b.x, a.y+b.y); }
__device__ __forceinline__ float2 csub(float2 a, float2 b){ return make_float2(a.x-b.x, a.y-b.y); }
__device__ __forceinline__ float2 cmul(float2 a, float2 b){ return make_float2(a.x*b.x-a.y*b.y, a.x*b.y+a.y*b.x); }
__device__ __forceinline__ float2 h2f(__half2 h){ return __half22float2(h); }
__device__ __forceinline__ __half2 f2h(float2 v){ return __float22half2_rn(v); }
__device__ __forceinline__ float cmag(float2 z){
  float x2 = z.x*z.x + z.y*z.y + 1e-36f;
  return x2 * rsqrtf(x2);                 // one MUFU.RSQ + mul
}
template<int S> __device__ __forceinline__ float2 mul_i(float2 a){
  return (S>0) ? make_float2(-a.y, a.x) : make_float2(a.y, -a.x);
}
template<int S> __device__ __forceinline__ void dft4(float2&a, float2&b, float2&c, float2&d){
  float2 t0=cadd(a,c), t1=csub(a,c), t2=cadd(b,d), t3=mul_i<S>(csub(b,d));
  a=cadd(t0,t2); c=csub(t0,t2); b=cadd(t1,t3); d=csub(t1,t3);
}
template<int S> __device__ __forceinline__ float2 w16(int m){
  float2 w = W16T[m];
  if (S < 0) w.y = -w.y;
  return w;
}
template<int S> __device__ __forceinline__ void fft16(float2 v[16]){
  #pragma unroll
  for (int n0=0; n0<4; n0++) dft4<S>(v[n0], v[n0+4], v[n0+8], v[n0+12]);
  #pragma unroll
  for (int n0=1; n0<4; n0++)
    #pragma unroll
    for (int k1=1; k1<4; k1++)
      v[n0+4*k1] = cmul(v[n0+4*k1], w16<S>(n0*k1));
  float2 o[16];
  #pragma unroll
  for (int k1=0; k1<4; k1++){
    float2 a=v[4*k1+0], b=v[4*k1+1], c=v[4*k1+2], d=v[4*k1+3];
    dft4<S>(a,b,c,d);
    o[k1]=a; o[k1+4]=b; o[k1+8]=c; o[k1+12]=d;
  }
  #pragma unroll
  for (int i=0;i<16;i++) v[i]=o[i];
}

template<int S> __device__ __forceinline__ void fft256_pad(float2 v[16], int i, float2* sm){
  fft16<S>(v);
  #pragma unroll
  for (int k1=1;k1<16;k1++){
    float2 w = TW[(i*k1*256)&65535];
    if (S<0) w.y = -w.y;
    v[k1] = cmul(v[k1], w);
  }
  #pragma unroll
  for (int k1=0;k1<16;k1++) sm[k1*16+i] = v[k1];
  __syncthreads();
  #pragma unroll
  for (int n0=0;n0<16;n0++) v[n0] = sm[i*16+n0];
  fft16<S>(v);
}

template<int S> __device__ __forceinline__ void fft256_swz(float2 v[16], int i, float2* sm){
  fft16<S>(v);
  #pragma unroll
  for (int k1=1;k1<16;k1++){
    float2 w = TW[(i*k1*256)&65535];
    if (S<0) w.y = -w.y;
    v[k1] = cmul(v[k1], w);
  }
  #pragma unroll
  for (int k1=0;k1<16;k1++) sm[k1*16 + ((i+k1)&15)] = v[k1];
  __syncthreads();
  #pragma unroll
  for (int n0=0;n0<16;n0++) v[n0] = sm[i*16 + ((n0+i)&15)];
  fft16<S>(v);
}

__device__ __forceinline__ void conv_partial(const float* u_s, const float* gf_s,
                                             int bx, int m, float* sp)
{
  float acc = 0.0f;
  #pragma unroll
  for (int f2=0; f2<16; f2++){
    const int q = bx*16 + f2 + 768;
    #pragma unroll
    for (int d=-3; d<=3; d++){
      int tap = d*256 + q;
      if (tap >= 0 && tap <= 1536)
        acc += gf_s[tap] * u_s[f2*257 + ((m + d) & 255)];
    }
  }
  sp[bx*256 + m] = acc;
}

// ---------------- setup kernels ----------------
__global__ void k_tw(){
  int k = blockIdx.x*blockDim.x + threadIdx.x;
  double a = 6.283185307179586476925286766559 * (double)k / 65536.0;
  TW[k] = make_float2((float)cos(a), (float)sin(a));
}
__global__ void k_g(){
  int i = blockIdx.x*blockDim.x + threadIdx.x;
  if (i >= GTAPS) return;
  int tt = i - LG; if (tt < 0) tt = -tt;
  const float invden = 1.0f/(65536.0f*(0.35f/256.0f));
  float acc = 1.0f;
  for (int k=1; k<=KPHI; k++){
    float z = (float)k * invden;
    float p = expf(-0.5f*z*z);
    int m = (k*tt) & 65535;
    acc += 2.0f * p * TW[m].x;
  }
  GF[i] = acc * INV_N;
}
__global__ void k_ps1(){
  int idx = blockIdx.x*blockDim.x + threadIdx.x;   // 64*65536 threads
  int ch = idx >> 16, k = idx & 65535;
  float xi   = 0.35f * exp2f(-(float)ch * 0.125f);
  float invs = 8.0f / xi;
  float fn = (k < 32768) ? (float)k * INV_N : ((float)k - 65536.0f) * INV_N;
  float z = (fn - xi) * invs;
  PS1[idx] = expf(-0.5f*z*z);
}
__global__ void k_ps2(){
  int idx = blockIdx.x*blockDim.x + threadIdx.x;   // 8*65536 threads
  int j2 = idx >> 16, k = idx & 65535;
  float xi   = 0.35f * exp2f(-(float)j2);
  float invs = 1.0f / (0.6f * xi);
  float fn = (k < 32768) ? (float)k * INV_N : ((float)k - 65536.0f) * INV_N;
  float z = (fn - xi) * invs;
  PS2[idx] = expf(-0.5f*z*z);
}

// ---------------- FFT pass kernels ----------------
__global__ void __launch_bounds__(256) k_fwd_col_x(const float* __restrict__ x,
                                                   float2* __restrict__ out)
{
  __shared__ float2 sm[16*257];
  const int f = threadIdx.x & 15, i = threadIdx.x >> 4;
  const int col = blockIdx.x*16 + f;
  const size_t base = (size_t)blockIdx.y * NF;
  float2 v[16];
  #pragma unroll
  for (int r=0;r<16;r++) v[r] = make_float2(x[base + (r*16+i)*256 + col], 0.0f);
  fft256_pad<-1>(v, i, sm + f*257);
  #pragma unroll
  for (int k2=0;k2<16;k2++){
    int K1 = k2*16 + i;
    float2 w = TW[(col*K1)&65535]; w.y = -w.y;
    out[base + K1*256 + col] = cmul(v[k2], w);
  }
}

__global__ void __launch_bounds__(256) k_fwd_row(const float2* __restrict__ in,
                                                 float2* __restrict__ out)
{
  __shared__ float2 sm[16*256];
  const int i = threadIdx.x & 15, f = threadIdx.x >> 4;
  const int row = blockIdx.x*16 + f;
  const size_t base = (size_t)blockIdx.y * NF;
  float2 v[16];
  #pragma unroll
  for (int r=0;r<16;r++) v[r] = in[base + row*256 + r*16 + i];
  fft256_swz<-1>(v, i, sm + f*256);
  #pragma unroll
  for (int k2=0;k2<16;k2++) out[base + row*256 + k2*16 + i] = v[k2];
}

// row pass: fp32 in -> fp16 u1f (x 0.25)
__global__ void __launch_bounds__(256) k_fwd_row_u1(const float2* __restrict__ in,
                                                    __half2* __restrict__ out)
{
  __shared__ float2 sm[16*256];
  const int i = threadIdx.x & 15, f = threadIdx.x >> 4;
  const int row = blockIdx.x*16 + f;
  const size_t base = (size_t)blockIdx.y * NF;
  float2 v[16];
  #pragma unroll
  for (int r=0;r<16;r++) v[r] = in[base + row*256 + r*16 + i];
  fft256_swz<-1>(v, i, sm + f*256);
  #pragma unroll
  for (int k2=0;k2<16;k2++){
    float2 o = v[k2];
    out[base + row*256 + k2*16 + i] = f2h(make_float2(o.x*0.25f, o.y*0.25f));
  }
}

// FO inverse pass A: table-based psi1, arithmetic band prune, no expf.
__global__ void __launch_bounds__(256) k_invA1(const float2* __restrict__ in,
                                               float2* __restrict__ out)
{
  __shared__ float2 sm[16*256];
  const int i = threadIdx.x & 15, f = threadIdx.x >> 4;
  const int K1 = blockIdx.x*16 + f;
  const int ti = blockIdx.y;
  const int b = ti >> 6, ch = ti & 63;
  const float xi   = 0.35f * exp2f(-(float)ch * 0.125f);
  const float invs = 8.0f / xi;
  const float2* src = in + (size_t)b*NF;
  const float*  ps  = PS1 + (size_t)ch*NF;

  float2 v[16];
  #pragma unroll
  for (int r=0;r<16;r++){
    int k = (r*16 + i)*256 + K1;
    float fn = (k < 32768) ? (float)k * INV_N : ((float)k - 65536.0f) * INV_N;
    float z = (fn - xi) * invs;
    if (fabsf(z) < ZCUT){
      float g = ps[k];
      float2 X = src[K1*256 + (r*16+i)];
      float s = g * INV_N;
      v[r] = make_float2(X.x*s, X.y*s);
    } else v[r] = make_float2(0.0f, 0.0f);
  }
  fft256_swz<1>(v, i, sm + f*256);
  #pragma unroll
  for (int k2=0;k2<16;k2++){
    int n2 = k2*16 + i;
    out[(size_t)ti*NF + K1*256 + n2] = cmul(v[k2], TW[(n2*K1)&65535]);
  }
}

// SO inverse pass A: table-based psi2, s = g*16/N (undo u1f 1/4, carry 4x).
__global__ void __launch_bounds__(256) k_invA2(const __half2* __restrict__ in,
                                               __half2* __restrict__ out)
{
  __shared__ float2 sm[16*256];
  const int i = threadIdx.x & 15, f = threadIdx.x >> 4;
  const int K1 = blockIdx.x*16 + f;
  const int ti = blockIdx.y;
  const int b = ti / NSEC;
  const int s0 = ti - b*NSEC;
  int j2 = 1;
  #pragma unroll
  for (int q=1; q<7; q++) if (s0 >= 4*q*(q+1)) j2 = q+1;
  const int ch = s0 - 4*j2*(j2-1);
  const float xi   = 0.35f * exp2f(-(float)j2);
  const float invs = 1.0f / (0.6f * xi);
  const __half2* src = in + ((size_t)b*JQ + ch)*NF;
  const float*   ps  = PS2 + (size_t)j2*NF;

  float2 v[16];
  #pragma unroll
  for (int r=0;r<16;r++){
    int k = (r*16 + i)*256 + K1;
    float fn = (k < 32768) ? (float)k * INV_N : ((float)k - 65536.0f) * INV_N;
    float z = (fn - xi) * invs;
    if (fabsf(z) < ZCUT){
      float g = ps[k];
      float2 X = h2f(src[K1*256 + (r*16+i)]);
      float s = g * (16.0f*INV_N);
      v[r] = make_float2(X.x*s, X.y*s);
    } else v[r] = make_float2(0.0f, 0.0f);
  }
  fft256_swz<1>(v, i, sm + f*256);
  #pragma unroll
  for (int k2=0;k2<16;k2++){
    int n2 = k2*16 + i;
    out[(size_t)ti*NF + K1*256 + n2] = f2h(cmul(v[k2], TW[(n2*K1)&65535]));
  }
}

// FO pass B: col IFFT -> |.| -> lowpass partial -> col FFT -> twiddle
__global__ void __launch_bounds__(256) k_fo_b(const float2* __restrict__ T,
                                              float2* __restrict__ out,
                                              float* __restrict__ sp1)
{
  __shared__ __align__(16) char smraw[16*257*sizeof(float2)];
  float2* sm   = (float2*)smraw;
  float*  u_s  = (float*)smraw;
  float*  gf_s = (float*)smraw + 16*257;

  const int f = threadIdx.x & 15, i = threadIdx.x >> 4;
  const int tid = threadIdx.x;
  const int n2 = blockIdx.x*16 + f;
  const size_t base = (size_t)blockIdx.y * NF;
  float2 v[16];
  #pragma unroll
  for (int r=0;r<16;r++) v[r] = T[base + (r*16+i)*256 + n2];
  fft256_pad<1>(v, i, sm + f*257);
  __syncthreads();
  #pragma unroll
  for (int k2=0;k2<16;k2++)
    u_s[f*257 + k2*16 + i] = cmag(v[k2]);
  for (int t=tid; t<GTAPS; t+=256) gf_s[t] = GF[t];
  __syncthreads();
  conv_partial(u_s, gf_s, blockIdx.x, tid, sp1 + (size_t)blockIdx.y*4096);
  __syncthreads();
  #pragma unroll
  for (int r=0;r<16;r++) v[r] = make_float2(u_s[f*257 + r*16 + i], 0.0f);
  __syncthreads();
  fft256_pad<-1>(v, i, sm + f*257);
  #pragma unroll
  for (int k2=0;k2<16;k2++){
    int K1 = k2*16 + i;
    float2 w = TW[(n2*K1)&65535]; w.y = -w.y;
    out[base + K1*256 + n2] = cmul(v[k2], w);
  }
}

// SO pass B: col IFFT -> 0.25*|.| -> lowpass partial
__global__ void __launch_bounds__(256) k_invB_abs(const __half2* __restrict__ T,
                                                  float* __restrict__ sp2)
{
  __shared__ __align__(16) char smraw[16*257*sizeof(float2)];
  float2* sm   = (float2*)smraw;
  float*  u_s  = (float*)smraw;
  float*  gf_s = (float*)smraw + 16*257;

  const int f = threadIdx.x & 15, i = threadIdx.x >> 4;
  const int tid = threadIdx.x;
  const int n2 = blockIdx.x*16 + f;
  const size_t base = (size_t)blockIdx.y * NF;
  float2 v[16];
  #pragma unroll
  for (int r=0;r<16;r++) v[r] = h2f(T[base + (r*16+i)*256 + n2]);
  fft256_pad<1>(v, i, sm + f*257);
  __syncthreads();
  #pragma unroll
  for (int k2=0;k2<16;k2++)
    u_s[f*257 + k2*16 + i] = 0.25f*cmag(v[k2]);
  for (int t=tid; t<GTAPS; t+=256) gf_s[t] = GF[t];
  __syncthreads();
  conv_partial(u_s, gf_s, blockIdx.x, tid, sp2 + (size_t)blockIdx.y*4096);
}

// ---------------- S0 conv ----------------
#define CONV_OUT 32
#define CONV_WIN ((CONV_OUT-1)*256 + GTAPS)
__global__ void __launch_bounds__(256) k_conv_x(const float* __restrict__ x,
                                                float* __restrict__ out)
{
  const int grp = blockIdx.x, b = blockIdx.y;
  const float* src = x + (size_t)b*NF;
  __shared__ float win[CONV_WIN + 3];
  __shared__ float gs[GTAPS];
  const int tid = threadIdx.x;
  const int w0 = grp*(CONV_OUT*256) - LG;
  for (int i=tid; i<CONV_WIN; i+=256) win[i] = src[(w0 + i) & 65535];
  for (int i=tid; i<GTAPS; i+=256) gs[i] = GF[i];
  __syncthreads();
  const int warp = tid >> 5, lane = tid & 31;
  #pragma unroll
  for (int oo=0; oo<CONV_OUT/8; oo++){
    const int o = warp*(CONV_OUT/8) + oo;
    const int off = o * 256;
    float acc = 0.0f;
    for (int i=lane; i<GTAPS; i+=32) acc += gs[i] * win[off + i];
    #pragma unroll
    for (int d=16; d; d>>=1) acc += __shfl_down_sync(0xffffffffu, acc, d);
    if (lane == 0){
      int n = grp*CONV_OUT + o;
      float mag = sqrtf(acc*acc + 1e-8f);
      out[(size_t)b*NCHAN*256 + n] = logf(mag + 1e-8f);
    }
  }
}

// ---------------- epilogue ----------------
__global__ void __launch_bounds__(256) k_log(const float* __restrict__ sp1,
                                             const float* __restrict__ sp2,
                                             float* __restrict__ out)
{
  const int row = blockIdx.x;
  const int b = row / 288, cm1 = row - b*288;
  const int m = threadIdx.x;
  const float* base = (cm1 < 64)
    ? sp1 + (size_t)(b*JQ   + cm1     )*4096
    : sp2 + (size_t)(b*NSEC + cm1 - 64)*4096;
  float S = 0.0f;
  #pragma unroll
  for (int k=0;k<16;k++) S += base[k*256 + m];
  float mag = sqrtf(S*S + 1e-8f);
  out[((size_t)b*NCHAN + 1 + cm1)*256 + m] = logf(mag + 1e-8f);
}

__global__ void k_zero(float* p, int n){
  int i = blockIdx.x*blockDim.x + threadIdx.x;
  if (i < n) p[i] = 0.0f;
}

// ---------------- launch ----------------
extern "C" void kernel_launch(void* const* d_in, const int* in_sizes, int n_in,
                              void* d_out, int out_size)
{
  (void)in_sizes; (void)n_in;
  const float* x = (const float*)d_in[0];
  float* out = (float*)d_out;

  float2 *xtmp, *xf, *p1a, *p1b;
  __half2 *p2, *u1f;
  float *sp1, *sp2;
  cudaGetSymbolAddress((void**)&xtmp, d_xtmp);
  cudaGetSymbolAddress((void**)&xf,   d_xf);
  cudaGetSymbolAddress((void**)&p1a,  d_p1a);
  cudaGetSymbolAddress((void**)&p1b,  d_p1b);
  cudaGetSymbolAddress((void**)&p2,   d_p2);
  cudaGetSymbolAddress((void**)&u1f,  d_u1f);
  cudaGetSymbolAddress((void**)&sp1,  d_sp1);
  cudaGetSymbolAddress((void**)&sp2,  d_sp2);

  k_tw <<<256,   256>>>();
  k_g  <<<7,     256>>>();
  k_ps1<<<16384, 256>>>();
  k_ps2<<<2048,  256>>>();

  // forward FFT of x
  k_fwd_col_x<<<dim3(16,8), 256>>>(x, xtmp);
  k_fwd_row  <<<dim3(16,8), 256>>>(xtmp, xf);

  // first order
  k_invA1     <<<dim3(16,512), 256>>>(xf, p1a);
  k_fo_b      <<<dim3(16,512), 256>>>(p1a, p1b, sp1);
  k_fwd_row_u1<<<dim3(16,512), 256>>>(p1b, u1f);

  // second order
  k_invA2   <<<dim3(16,1792), 256>>>(u1f, p2);
  k_invB_abs<<<dim3(16,1792), 256>>>(p2, sp2);

  // S0 + epilogue
  k_conv_x<<<dim3(8, NB), 256>>>(x, out);
  k_log   <<<2304, 256>>>(sp1, sp2, out);

  int half = out_size / 2;
  k_zero<<<(half + 255)/256, 256>>>(out + half, half);
}

// round 9
// speedup vs baseline: 1.4740x; 1.3762x over previous
#include <cuda_runtime.h>
#include <cuda_fp16.h>
#include <math.h>
#include <stdint.h>

#define NF 65536
#define NB 8
#define JQ 64
#define NSEC 224
#define NCHAN 289
#define LG 768
#define GTAPS 1537
#define KPHI 1024
#define INV_N (1.0f/65536.0f)
#define ZCUT 7.4395f       // e^{-0.5*z^2} ~ 1e-12
#define TS2 120            // full-res SO sections per batch (j2<=5)

// ---------------- static device storage ----------------
static __device__ float2  TW[NF];
static __device__ float   GF[GTAPS];
static __device__ float2  d_xtmp[  8u*65536u];
static __device__ float2  d_xf  [  8u*65536u];
static __device__ float2  d_p1a [ 512u*65536u];
static __device__ float2  d_p1b [ 512u*65536u];
static __device__ __half2 d_p2  [(size_t)960u*65536u];  // SO passA->passB (fp16, 4x true)
static __device__ __half2 d_u1f [ 512u*65536u];         // FFT(|U1|) fp16, scaled 1/4
static __device__ float   d_sp1 [  512u*4096u];
static __device__ float   d_sp2 [ 1792u*4096u];

static __device__ const float2 W16T[16] = {
  { 1.0f, 0.0f},
  { 0.9238795325112867f, 0.3826834323650898f},
  { 0.7071067811865476f, 0.7071067811865476f},
  { 0.3826834323650898f, 0.9238795325112867f},
  { 0.0f, 1.0f},
  {-0.3826834323650898f, 0.9238795325112867f},
  {-0.7071067811865476f, 0.7071067811865476f},
  {-0.9238795325112867f, 0.3826834323650898f},
  {-1.0f, 0.0f},
  {-0.9238795325112867f,-0.3826834323650898f},
  {-0.7071067811865476f,-0.7071067811865476f},
  {-0.3826834323650898f,-0.9238795325112867f},
  { 0.0f,-1.0f},
  { 0.3826834323650898f,-0.9238795325112867f},
  { 0.7071067811865476f,-0.7071067811865476f},
  { 0.9238795325112867f,-0.3826834323650898f}
};

// ---------------- helpers ----------------
__device__ __forceinline__ float2 cadd(float2 a, float2 b){ return make_float2(a.x+b.x, a.y+b.y); }
__device__ __forceinline__ float2 csub(float2 a, float2 b){ return make_float2(a.x-b.x, a.y-b.y); }
__device__ __forceinline__ float2 cmul(float2 a, float2 b){ return make_float2(a.x*b.x-a.y*b.y, a.x*b.y+a.y*b.x); }
__device__ __forceinline__ float2 h2f(__half2 h){ return __half22float2(h); }
__device__ __forceinline__ __half2 f2h(float2 v){ return __float22half2_rn(v); }
__device__ __forceinline__ float cmag(float2 z){
  float x2 = z.x*z.x + z.y*z.y + 1e-36f;
  return x2 * rsqrtf(x2);
}
template<int S> __device__ __forceinline__ float2 mul_i(float2 a){
  return (S>0) ? make_float2(-a.y, a.x) : make_float2(a.y, -a.x);
}
template<int S> __device__ __forceinline__ void dft4(float2&a, float2&b, float2&c, float2&d){
  float2 t0=cadd(a,c), t1=csub(a,c), t2=cadd(b,d), t3=mul_i<S>(csub(b,d));
  a=cadd(t0,t2); c=csub(t0,t2); b=cadd(t1,t3); d=csub(t1,t3);
}
template<int S> __device__ __forceinline__ float2 w16(int m){
  float2 w = W16T[m];
  if (S < 0) w.y = -w.y;
  return w;
}
template<int S> __device__ __forceinline__ void fft16(float2 v[16]){
  #pragma unroll
  for (int n0=0; n0<4; n0++) dft4<S>(v[n0], v[n0+4], v[n0+8], v[n0+12]);
  #pragma unroll
  for (int n0=1; n0<4; n0++)
    #pragma unroll
    for (int k1=1; k1<4; k1++)
      v[n0+4*k1] = cmul(v[n0+4*k1], w16<S>(n0*k1));
  float2 o[16];
  #pragma unroll
  for (int k1=0; k1<4; k1++){
    float2 a=v[4*k1+0], b=v[4*k1+1], c=v[4*k1+2], d=v[4*k1+3];
    dft4<S>(a,b,c,d);
    o[k1]=a; o[k1+4]=b; o[k1+8]=c; o[k1+12]=d;
  }
  #pragma unroll
  for (int i=0;i<16;i++) v[i]=o[i];
}

// padded-row transpose (f in LOW 4 bits of tid; cross-warp -> block barrier)
template<int S> __device__ __forceinline__ void fft256_pad(float2 v[16], int i, float2* sm){
  fft16<S>(v);
  #pragma unroll
  for (int k1=1;k1<16;k1++){
    float2 w = TW[(i*k1*256)&65535];
    if (S<0) w.y = -w.y;
    v[k1] = cmul(v[k1], w);
  }
  #pragma unroll
  for (int k1=0;k1<16;k1++) sm[k1*16+i] = v[k1];
  __syncthreads();
  #pragma unroll
  for (int n0=0;n0<16;n0++) v[n0] = sm[i*16+n0];
  fft16<S>(v);
}

// swizzled transpose (i in LOW 4 bits: partners are a half-warp -> warp sync only)
template<int S> __device__ __forceinline__ void fft256_swz(float2 v[16], int i, float2* sm){
  fft16<S>(v);
  #pragma unroll
  for (int k1=1;k1<16;k1++){
    float2 w = TW[(i*k1*256)&65535];
    if (S<0) w.y = -w.y;
    v[k1] = cmul(v[k1], w);
  }
  #pragma unroll
  for (int k1=0;k1<16;k1++) sm[k1*16 + ((i+k1)&15)] = v[k1];
  __syncwarp();
  #pragma unroll
  for (int n0=0;n0<16;n0++) v[n0] = sm[i*16 + ((n0+i)&15)];
  fft16<S>(v);
}

__device__ __forceinline__ void conv_partial(const float* u_s, const float* gf_s,
                                             int bx, int m, float* sp)
{
  float acc = 0.0f;
  #pragma unroll
  for (int f2=0; f2<16; f2++){
    const int q = bx*16 + f2 + 768;
    #pragma unroll
    for (int d=-3; d<=3; d++){
      int tap = d*256 + q;
      if (tap >= 0 && tap <= 1536)
        acc += gf_s[tap] * u_s[f2*257 + ((m + d) & 255)];
    }
  }
  sp[bx*256 + m] = acc;
}

// ---------------- setup kernels ----------------
__global__ void k_tw(){
  int k = blockIdx.x*blockDim.x + threadIdx.x;
  double a = 6.283185307179586476925286766559 * (double)k / 65536.0;
  TW[k] = make_float2((float)cos(a), (float)sin(a));
}
__global__ void k_g(){
  int i = blockIdx.x*blockDim.x + threadIdx.x;
  if (i >= GTAPS) return;
  int tt = i - LG; if (tt < 0) tt = -tt;
  const float invden = 1.0f/(65536.0f*(0.35f/256.0f));
  float acc = 1.0f;
  for (int k=1; k<=KPHI; k++){
    float z = (float)k * invden;
    float p = expf(-0.5f*z*z);
    int m = (k*tt) & 65535;
    acc += 2.0f * p * TW[m].x;
  }
  GF[i] = acc * INV_N;
}

// ---------------- FFT pass kernels ----------------
__global__ void __launch_bounds__(256) k_fwd_col_x(const float* __restrict__ x,
                                                   float2* __restrict__ out)
{
  __shared__ float2 sm[16*257];
  const int f = threadIdx.x & 15, i = threadIdx.x >> 4;
  const int col = blockIdx.x*16 + f;
  const size_t base = (size_t)blockIdx.y * NF;
  float2 v[16];
  #pragma unroll
  for (int r=0;r<16;r++) v[r] = make_float2(x[base + (r*16+i)*256 + col], 0.0f);
  fft256_pad<-1>(v, i, sm + f*257);
  #pragma unroll
  for (int k2=0;k2<16;k2++){
    int K1 = k2*16 + i;
    float2 w = TW[(col*K1)&65535]; w.y = -w.y;
    out[base + K1*256 + col] = cmul(v[k2], w);
  }
}

__global__ void __launch_bounds__(256) k_fwd_row(const float2* __restrict__ in,
                                                 float2* __restrict__ out)
{
  __shared__ float2 sm[16*256];
  const int i = threadIdx.x & 15, f = threadIdx.x >> 4;
  const int row = blockIdx.x*16 + f;
  const size_t base = (size_t)blockIdx.y * NF;
  float2 v[16];
  #pragma unroll
  for (int r=0;r<16;r++) v[r] = in[base + row*256 + r*16 + i];
  fft256_swz<-1>(v, i, sm + f*256);
  #pragma unroll
  for (int k2=0;k2<16;k2++) out[base + row*256 + k2*16 + i] = v[k2];
}

__global__ void __launch_bounds__(256) k_fwd_row_u1(const float2* __restrict__ in,
                                                    __half2* __restrict__ out)
{
  __shared__ float2 sm[16*256];
  const int i = threadIdx.x & 15, f = threadIdx.x >> 4;
  const int row = blockIdx.x*16 + f;
  const size_t base = (size_t)blockIdx.y * NF;
  float2 v[16];
  #pragma unroll
  for (int r=0;r<16;r++) v[r] = in[base + row*256 + r*16 + i];
  fft256_swz<-1>(v, i, sm + f*256);
  #pragma unroll
  for (int k2=0;k2<16;k2++){
    float2 o = v[k2];
    out[base + row*256 + k2*16 + i] = f2h(make_float2(o.x*0.25f, o.y*0.25f));
  }
}

// FO inverse pass A: inline psi1, band pruned.
__global__ void __launch_bounds__(256) k_invA1(const float2* __restrict__ in,
                                               float2* __restrict__ out)
{
  __shared__ float2 sm[16*256];
  const int i = threadIdx.x & 15, f = threadIdx.x >> 4;
  const int K1 = blockIdx.x*16 + f;
  const int ti = blockIdx.y;
  const int b = ti >> 6, ch = ti & 63;
  const float xi   = 0.35f * exp2f(-(float)ch * 0.125f);
  const float invs = 8.0f / xi;
  const float2* src = in + (size_t)b*NF;

  float2 v[16];
  #pragma unroll
  for (int r=0;r<16;r++){
    int k = (r*16 + i)*256 + K1;
    float fn = (k < 32768) ? (float)k * INV_N : ((float)k - 65536.0f) * INV_N;
    float z = (fn - xi) * invs;
    if (fabsf(z) < ZCUT){
      float g = expf(-0.5f*z*z);
      float2 X = src[K1*256 + (r*16+i)];
      float s = g * INV_N;
      v[r] = make_float2(X.x*s, X.y*s);
    } else v[r] = make_float2(0.0f, 0.0f);
  }
  fft256_swz<1>(v, i, sm + f*256);
  #pragma unroll
  for (int k2=0;k2<16;k2++){
    int n2 = k2*16 + i;
    out[(size_t)ti*NF + K1*256 + n2] = cmul(v[k2], TW[(n2*K1)&65535]);
  }
}

// SO inverse pass A (full-res sections only, j2<=5). s = g*16/N.
__global__ void __launch_bounds__(256) k_invA2(const __half2* __restrict__ in,
                                               __half2* __restrict__ out)
{
  __shared__ float2 sm[16*256];
  const int i = threadIdx.x & 15, f = threadIdx.x >> 4;
  const int K1 = blockIdx.x*16 + f;
  const int ti = blockIdx.y;
  const int b = ti / TS2;
  const int s0 = ti - b*TS2;
  int j2 = 1;
  #pragma unroll
  for (int q=1; q<5; q++) if (s0 >= 4*q*(q+1)) j2 = q+1;
  const int ch = s0 - 4*j2*(j2-1);
  const float xi   = 0.35f * exp2f(-(float)j2);
  const float invs = 1.0f / (0.6f * xi);
  const __half2* src = in + ((size_t)b*JQ + ch)*NF;

  float2 v[16];
  #pragma unroll
  for (int r=0;r<16;r++){
    int k = (r*16 + i)*256 + K1;
    float fn = (k < 32768) ? (float)k * INV_N : ((float)k - 65536.0f) * INV_N;
    float z = (fn - xi) * invs;
    if (fabsf(z) < ZCUT){
      float g = expf(-0.5f*z*z);
      float2 X = h2f(src[K1*256 + (r*16+i)]);
      float s = g * (16.0f*INV_N);
      v[r] = make_float2(X.x*s, X.y*s);
    } else v[r] = make_float2(0.0f, 0.0f);
  }
  fft256_swz<1>(v, i, sm + f*256);
  #pragma unroll
  for (int k2=0;k2<16;k2++){
    int n2 = k2*16 + i;
    out[(size_t)ti*NF + K1*256 + n2] = f2h(cmul(v[k2], TW[(n2*K1)&65535]));
  }
}

// FO pass B: col IFFT -> |.| -> lowpass partial -> col FFT -> twiddle
__global__ void __launch_bounds__(256) k_fo_b(const float2* __restrict__ T,
                                              float2* __restrict__ out,
                                              float* __restrict__ sp1)
{
  __shared__ __align__(16) char smraw[16*257*sizeof(float2)];
  float2* sm   = (float2*)smraw;
  float*  u_s  = (float*)smraw;
  float*  gf_s = (float*)smraw + 16*257;

  const int f = threadIdx.x & 15, i = threadIdx.x >> 4;
  const int tid = threadIdx.x;
  const int n2 = blockIdx.x*16 + f;
  const size_t base = (size_t)blockIdx.y * NF;
  float2 v[16];
  #pragma unroll
  for (int r=0;r<16;r++) v[r] = T[base + (r*16+i)*256 + n2];
  fft256_pad<1>(v, i, sm + f*257);
  __syncthreads();
  #pragma unroll
  for (int k2=0;k2<16;k2++)
    u_s[f*257 + k2*16 + i] = cmag(v[k2]);
  for (int t=tid; t<GTAPS; t+=256) gf_s[t] = GF[t];
  __syncthreads();
  conv_partial(u_s, gf_s, blockIdx.x, tid, sp1 + (size_t)blockIdx.y*4096);
  __syncthreads();
  #pragma unroll
  for (int r=0;r<16;r++) v[r] = make_float2(u_s[f*257 + r*16 + i], 0.0f);
  __syncthreads();
  fft256_pad<-1>(v, i, sm + f*257);
  #pragma unroll
  for (int k2=0;k2<16;k2++){
    int K1 = k2*16 + i;
    float2 w = TW[(n2*K1)&65535]; w.y = -w.y;
    out[base + K1*256 + n2] = cmul(v[k2], w);
  }
}

// SO pass B (full-res sections): col IFFT -> 0.25*|.| -> lowpass partial
__global__ void __launch_bounds__(256) k_invB_abs(const __half2* __restrict__ T,
                                                  float* __restrict__ sp2)
{
  __shared__ __align__(16) char smraw[16*257*sizeof(float2)];
  float2* sm   = (float2*)smraw;
  float*  u_s  = (float*)smraw;
  float*  gf_s = (float*)smraw + 16*257;

  const int f = threadIdx.x & 15, i = threadIdx.x >> 4;
  const int tid = threadIdx.x;
  const int n2 = blockIdx.x*16 + f;
  const int ti = blockIdx.y;
  const int b = ti / TS2, s0 = ti - b*TS2;
  const size_t base = (size_t)ti * NF;
  float2 v[16];
  #pragma unroll
  for (int r=0;r<16;r++) v[r] = h2f(T[base + (r*16+i)*256 + n2]);
  fft256_pad<1>(v, i, sm + f*257);
  __syncthreads();
  #pragma unroll
  for (int k2=0;k2<16;k2++)
    u_s[f*257 + k2*16 + i] = 0.25f*cmag(v[k2]);
  for (int t=tid; t<GTAPS; t+=256) gf_s[t] = GF[t];
  __syncthreads();
  conv_partial(u_s, gf_s, blockIdx.x, tid, sp2 + (size_t)(b*NSEC + s0)*4096);
}

// Fused decimated SO for j2 in {6,7}: one block per (section, batch).
// Load pruned band folded to N'=4096 -> 4096-pt IFFT (256x16) -> |.| ->
// decimated lowpass (step 16) -> final S2 row into sp2 slot 0 (others zeroed).
__global__ void __launch_bounds__(256) k_so4096(const __half2* __restrict__ u1f,
                                                float* __restrict__ sp2)
{
  extern __shared__ char dyn[];
  float2* sm  = (float2*)dyn;               // 16*257 f2  (pass A transpose)
  float2* sA  = (float2*)dyn + 4112;        // 256*17 f2  (pass A -> pass B)
  float*  sU  = (float*)dyn;                // overlay sm: 4096+128 floats
  float*  g16 = (float*)dyn + 4300;         // 97 floats

  const int t = threadIdx.x;
  const int f = t & 15, i = t >> 4;
  const int s0 = TS2 + blockIdx.x;          // 120..223
  const int b  = blockIdx.y;
  const int j2 = (s0 >= 168) ? 7 : 6;
  const int ch = s0 - 4*j2*(j2-1);
  const float xi   = 0.35f * exp2f(-(float)j2);
  const float invs = 1.0f/(0.6f*xi);
  const float kcf  = xi * 65536.0f;
  const __half2* src = u1f + ((size_t)b*JQ + ch)*NF;

  // pass A: 16 x 256-pt inverse FFTs over kA (k' = kA*16 + kB, kB = f)
  float2 v[16];
  #pragma unroll
  for (int r=0;r<16;r++){
    int kp = r*256 + i*16 + f;
    int d  = (int)floorf((kcf - (float)kp) * (1.0f/4096.0f) + 0.5f);
    int k  = (kp + (d << 12)) & 65535;
    float fn = (k < 32768) ? (float)k*INV_N : ((float)k - 65536.0f)*INV_N;
    float z = (fn - xi)*invs;
    if (fabsf(z) < ZCUT){
      float g = expf(-0.5f*z*z);
      float2 X = h2f(src[(k & 255)*256 + (k >> 8)]);
      float s = g * (4.0f*INV_N);           // 4x undoes u1f's 0.25
      v[r] = make_float2(X.x*s, X.y*s);
    } else v[r] = make_float2(0.0f, 0.0f);
  }
  fft256_pad<1>(v, i, sm + f*257);
  #pragma unroll
  for (int k2=0;k2<16;k2++){
    int a = k2*16 + i;
    sA[a*17 + f] = cmul(v[k2], TW[(a*f*16)&65535]);   // e^{+2pi i a kB/4096}
  }
  __syncthreads();

  // pass B: per-thread 16-pt inverse FFT over kB; y[t + 256*bb] = w[bb]
  {
    float2 w[16];
    #pragma unroll
    for (int kB=0;kB<16;kB++) w[kB] = sA[t*17 + kB];
    fft16<1>(w);
    #pragma unroll
    for (int bb=0;bb<16;bb++){
      int m = t + 256*bb;
      sU[m + (m>>5)] = cmag(w[bb]);
    }
  }
  if (t < 97) g16[t] = GF[16*t];
  __syncthreads();

  // decimated lowpass: S(p=t) = 16 * sum_j GF[16j] * u'(16t + j - 48)
  float acc = 0.0f;
  for (int j=0;j<97;j++){
    int m = (16*t + j - 48) & 4095;
    acc += g16[j] * sU[m + (m>>5)];
  }
  float* o = sp2 + (size_t)(b*NSEC + s0)*4096;
  o[t] = 16.0f*acc;
  #pragma unroll
  for (int k=1;k<16;k++) o[k*256 + t] = 0.0f;
}

// ---------------- S0 conv ----------------
#define CONV_OUT 32
#define CONV_WIN ((CONV_OUT-1)*256 + GTAPS)
__global__ void __launch_bounds__(256) k_conv_x(const float* __restrict__ x,
                                                float* __restrict__ out)
{
  const int grp = blockIdx.x, b = blockIdx.y;
  const float* src = x + (size_t)b*NF;
  __shared__ float win[CONV_WIN + 3];
  __shared__ float gs[GTAPS];
  const int tid = threadIdx.x;
  const int w0 = grp*(CONV_OUT*256) - LG;
  for (int i=tid; i<CONV_WIN; i+=256) win[i] = src[(w0 + i) & 65535];
  for (int i=tid; i<GTAPS; i+=256) gs[i] = GF[i];
  __syncthreads();
  const int warp = tid >> 5, lane = tid & 31;
  #pragma unroll
  for (int oo=0; oo<CONV_OUT/8; oo++){
    const int o = warp*(CONV_OUT/8) + oo;
    const int off = o * 256;
    float acc = 0.0f;
    for (int i=lane; i<GTAPS; i+=32) acc += gs[i] * win[off + i];
    #pragma unroll
    for (int d=16; d; d>>=1) acc += __shfl_down_sync(0xffffffffu, acc, d);
    if (lane == 0){
      int n = grp*CONV_OUT + o;
      float mag = sqrtf(acc*acc + 1e-8f);
      out[(size_t)b*NCHAN*256 + n] = logf(mag + 1e-8f);
    }
  }
}

// ---------------- epilogue ----------------
__global__ void __launch_bounds__(256) k_log(const float* __restrict__ sp1,
                                             const float* __restrict__ sp2,
                                             float* __restrict__ out)
{
  const int row = blockIdx.x;
  const int b = row / 288, cm1 = row - b*288;
  const int m = threadIdx.x;
  const float* base = (cm1 < 64)
    ? sp1 + (size_t)(b*JQ   + cm1     )*4096
    : sp2 + (size_t)(b*NSEC + cm1 - 64)*4096;
  float S = 0.0f;
  #pragma unroll
  for (int k=0;k<16;k++) S += base[k*256 + m];
  float mag = sqrtf(S*S + 1e-8f);
  out[((size_t)b*NCHAN + 1 + cm1)*256 + m] = logf(mag + 1e-8f);
}

__global__ void k_zero(float* p, int n){
  int i = blockIdx.x*blockDim.x + threadIdx.x;
  if (i < n) p[i] = 0.0f;
}

// ---------------- launch ----------------
extern "C" void kernel_launch(void* const* d_in, const int* in_sizes, int n_in,
                              void* d_out, int out_size)
{
  (void)in_sizes; (void)n_in;
  const float* x = (const float*)d_in[0];
  float* out = (float*)d_out;

  float2 *xtmp, *xf, *p1a, *p1b;
  __half2 *p2, *u1f;
  float *sp1, *sp2;
  cudaGetSymbolAddress((void**)&xtmp, d_xtmp);
  cudaGetSymbolAddress((void**)&xf,   d_xf);
  cudaGetSymbolAddress((void**)&p1a,  d_p1a);
  cudaGetSymbolAddress((void**)&p1b,  d_p1b);
  cudaGetSymbolAddress((void**)&p2,   d_p2);
  cudaGetSymbolAddress((void**)&u1f,  d_u1f);
  cudaGetSymbolAddress((void**)&sp1,  d_sp1);
  cudaGetSymbolAddress((void**)&sp2,  d_sp2);

  static int smem_set = 0;
  if (!smem_set){
    cudaFuncSetAttribute(k_so4096, cudaFuncAttributeMaxDynamicSharedMemorySize, 69632);
    smem_set = 1;
  }

  k_tw<<<256, 256>>>();
  k_g <<<7,   256>>>();

  // forward FFT of x
  k_fwd_col_x<<<dim3(16,8), 256>>>(x, xtmp);
  k_fwd_row  <<<dim3(16,8), 256>>>(xtmp, xf);

  // first order
  k_invA1     <<<dim3(16,512), 256>>>(xf, p1a);
  k_fo_b      <<<dim3(16,512), 256>>>(p1a, p1b, sp1);
  k_fwd_row_u1<<<dim3(16,512), 256>>>(p1b, u1f);

  // second order, full-res sections (j2 <= 5): 120 per batch
  k_invA2   <<<dim3(16, 8*TS2), 256>>>(u1f, p2);
  k_invB_abs<<<dim3(16, 8*TS2), 256>>>(p2, sp2);

  // second order, decimated sections (j2 in {6,7}): fused single-block
  k_so4096<<<dim3(NSEC-TS2, NB), 256, 69632>>>(u1f, sp2);

  // S0 + epilogue
  k_conv_x<<<dim3(8, NB), 256>>>(x, out);
  k_log   <<<2304, 256>>>(sp1, sp2, out);

  int half = out_size / 2;
  k_zero<<<(half + 255)/256, 256>>>(out + half, half);
}